// round 1
// baseline (speedup 1.0000x reference)
#include <cuda_runtime.h>

#define NN 100000
#define EE 1600000

// Scratch (allocation-free rule: __device__ globals)
__device__ float g_k [NN * 64];
__device__ float g_q [NN * 64];
__device__ float g_hw[NN * 64];
__device__ float g_z [NN * 4];

// ---------------------------------------------------------------------------
// Kernel 1: k = h@Wk, q = h@Wq, hw = h@W   (three 64x64 projections, fused)
// 256 threads, 32 nodes/block. Weights transposed in smem (row stride 68 to
// kill float4 bank conflicts), h tile in smem, 8-node register blocking.
// ---------------------------------------------------------------------------
__global__ __launch_bounds__(256) void gemm3_kernel(
    const float* __restrict__ h,
    const float* __restrict__ Wk,
    const float* __restrict__ Wq,
    const float* __restrict__ Ww,
    int N)
{
    __shared__ float sWk[64 * 68];
    __shared__ float sWq[64 * 68];
    __shared__ float sWw[64 * 68];
    __shared__ float sh [32 * 68];

    const int tid = threadIdx.x;

    // Load weights transposed: sW[col*68 + i] = W[i*64 + col]
    for (int idx = tid; idx < 64 * 64; idx += 256) {
        int i = idx >> 6, c = idx & 63;
        sWk[c * 68 + i] = Wk[idx];
        sWq[c * 68 + i] = Wq[idx];
        sWw[c * 68 + i] = Ww[idx];
    }
    const int base = blockIdx.x * 32;
    for (int idx = tid; idx < 32 * 64; idx += 256) {
        int n = idx >> 6, c = idx & 63;
        int gn = base + n;
        sh[n * 68 + c] = (gn < N) ? h[(size_t)gn * 64 + c] : 0.f;
    }
    __syncthreads();

    const int grp = tid >> 6;   // 0..3  -> node sub-tile
    const int col = tid & 63;   // output column

    float ak[8], aq[8], aw[8];
#pragma unroll
    for (int n = 0; n < 8; n++) { ak[n] = aq[n] = aw[n] = 0.f; }

    const float4* wk4 = (const float4*)(sWk + col * 68);
    const float4* wq4 = (const float4*)(sWq + col * 68);
    const float4* ww4 = (const float4*)(sWw + col * 68);

#pragma unroll
    for (int i4 = 0; i4 < 16; i4++) {
        const float4 wk = wk4[i4];
        const float4 wq = wq4[i4];
        const float4 ww = ww4[i4];
#pragma unroll
        for (int n = 0; n < 8; n++) {
            const float4 hv = *(const float4*)(sh + (grp * 8 + n) * 68 + i4 * 4);
            ak[n] += hv.x * wk.x + hv.y * wk.y + hv.z * wk.z + hv.w * wk.w;
            aq[n] += hv.x * wq.x + hv.y * wq.y + hv.z * wq.z + hv.w * wq.w;
            aw[n] += hv.x * ww.x + hv.y * ww.y + hv.z * ww.z + hv.w * ww.w;
        }
    }

#pragma unroll
    for (int n = 0; n < 8; n++) {
        int gn = base + grp * 8 + n;
        if (gn < N) {
            size_t o = (size_t)gn * 64 + col;
            g_k [o] = ak[n];
            g_q [o] = aq[n];
            g_hw[o] = aw[n];
        }
    }
}

// ---------------------------------------------------------------------------
// Kernel 2: zero the per-node/per-head softmax denominators
// ---------------------------------------------------------------------------
__global__ void zero_z_kernel(int n)
{
    int i = blockIdx.x * blockDim.x + threadIdx.x;
    if (i < n) g_z[i] = 0.f;
}

// ---------------------------------------------------------------------------
// Kernel 3: fused edge pass. One warp per edge.
//   e[h]  = <k[src][16h:16h+16], q[dst][16h:16h+16]>
//   ex[h] = exp(e[h])            (max-subtraction dropped; see analysis)
//   z[dst,h]      += ex[h]                (red.add.f32)
//   out[dst,h,:]  += ex[h] * hw[src,:]    (red.global.add.v4.f32)
// ---------------------------------------------------------------------------
__device__ __forceinline__ void red4(float* p, float x, float y, float z, float w)
{
    asm volatile("red.global.add.v4.f32 [%0], {%1,%2,%3,%4};"
                 :: "l"(p), "f"(x), "f"(y), "f"(z), "f"(w) : "memory");
}

__global__ __launch_bounds__(256) void edge_kernel(
    const int* __restrict__ src,
    const int* __restrict__ dst,
    float* __restrict__ out,
    int E)
{
    const int gw   = (blockIdx.x * blockDim.x + threadIdx.x) >> 5;
    const int lane = threadIdx.x & 31;
    if (gw >= E) return;

    const int s = __ldg(src + gw);
    const int d = __ldg(dst + gw);

    const float* kp = g_k + (size_t)s * 64;
    const float* qp = g_q + (size_t)d * 64;

    // lanes 0..31 cover elements 0..31 (heads 0,1) in v1, 32..63 (heads 2,3) in v2
    float v1 = kp[lane]      * qp[lane];
    float v2 = kp[lane + 32] * qp[lane + 32];
#pragma unroll
    for (int off = 8; off > 0; off >>= 1) {
        v1 += __shfl_xor_sync(0xffffffffu, v1, off);
        v2 += __shfl_xor_sync(0xffffffffu, v2, off);
    }
    const float ex0 = __expf(__shfl_sync(0xffffffffu, v1, 0));
    const float ex1 = __expf(__shfl_sync(0xffffffffu, v1, 16));
    const float ex2 = __expf(__shfl_sync(0xffffffffu, v2, 0));
    const float ex3 = __expf(__shfl_sync(0xffffffffu, v2, 16));

    if (lane < 4) {
        float exl = (lane == 0) ? ex0 : (lane == 1) ? ex1 : (lane == 2) ? ex2 : ex3;
        atomicAdd(&g_z[(size_t)d * 4 + lane], exl);
    }

    // lane -> (head hh = lane/8, feature block f = (lane%8)*8): 8 floats per lane
    const int hh = lane >> 3;
    const int f  = (lane & 7) << 3;
    const float m = (hh == 0) ? ex0 : (hh == 1) ? ex1 : (hh == 2) ? ex2 : ex3;

    const float4 a0 = *(const float4*)(g_hw + (size_t)s * 64 + f);
    const float4 a1 = *(const float4*)(g_hw + (size_t)s * 64 + f + 4);

    float* op = out + (size_t)d * 256 + hh * 64 + f;
    red4(op,     a0.x * m, a0.y * m, a0.z * m, a0.w * m);
    red4(op + 4, a1.x * m, a1.y * m, a1.z * m, a1.w * m);
}

// ---------------------------------------------------------------------------
// Kernel 4: out[n, h*64+f] = out[n, h*64+f] / z[n,h] + b[f]   (float4 wide)
// ---------------------------------------------------------------------------
__global__ __launch_bounds__(256) void finalize_kernel(
    float* __restrict__ out,
    const float* __restrict__ b,
    int N)
{
    int idx = blockIdx.x * blockDim.x + threadIdx.x;  // over N*64 float4s
    if (idx >= N * 64) return;
    const int n  = idx >> 6;
    const int c4 = idx & 63;       // float4 index within the 256-wide row
    const int hh = c4 >> 4;
    const float zv  = g_z[n * 4 + hh];
    const float inv = (zv > 0.f) ? 1.f / zv : 0.f;

    float4 v  = ((float4*)out)[idx];
    const float4 bb = ((const float4*)b)[c4 & 15];
    v.x = v.x * inv + bb.x;
    v.y = v.y * inv + bb.y;
    v.z = v.z * inv + bb.z;
    v.w = v.w * inv + bb.w;
    ((float4*)out)[idx] = v;
}

// ---------------------------------------------------------------------------
extern "C" void kernel_launch(void* const* d_in, const int* in_sizes, int n_in,
                              void* d_out, int out_size)
{
    const float* h   = (const float*)d_in[0];
    const int*   src = (const int*)  d_in[1];
    const int*   dst = (const int*)  d_in[2];
    const float* Wk  = (const float*)d_in[3];
    const float* Wq  = (const float*)d_in[4];
    const float* Ww  = (const float*)d_in[5];
    const float* b   = (const float*)d_in[6];
    float*       out = (float*)d_out;

    const int N = in_sizes[0] / 64;
    const int E = in_sizes[1];

    cudaMemsetAsync(out, 0, (size_t)N * 256 * sizeof(float));
    zero_z_kernel<<<(N * 4 + 255) / 256, 256>>>(N * 4);
    gemm3_kernel<<<(N + 31) / 32, 256>>>(h, Wk, Wq, Ww, N);
    edge_kernel<<<(E + 7) / 8, 256>>>(src, dst, out, E);
    finalize_kernel<<<(N * 64 + 255) / 256, 256>>>(out, b, N);
}

// round 2
// speedup vs baseline: 2.6451x; 2.6451x over previous
#include <cuda_runtime.h>

#define NN 100000
#define EE 1600000

// Scratch (allocation-free rule: __device__ globals)
__device__ float g_kw [NN * 128];   // interleaved: [n][0:64]=k row, [n][64:128]=hw row
__device__ float g_q  [NN * 64];
__device__ int   g_cnt [NN];
__device__ int   g_roff[NN + 1];
__device__ int   g_cur [NN];
__device__ int   g_bsum[512];
__device__ int   g_boff[512];
__device__ int   g_esrc[EE];

// ---------------------------------------------------------------------------
// Kernel 1: k = h@Wk, q = h@Wq, hw = h@W  (three 64x64 projections, fused)
// ---------------------------------------------------------------------------
__global__ __launch_bounds__(256) void gemm3_kernel(
    const float* __restrict__ h,
    const float* __restrict__ Wk,
    const float* __restrict__ Wq,
    const float* __restrict__ Ww,
    int N)
{
    __shared__ float sWk[64 * 68];
    __shared__ float sWq[64 * 68];
    __shared__ float sWw[64 * 68];
    __shared__ float sh [32 * 68];

    const int tid = threadIdx.x;

    for (int idx = tid; idx < 64 * 64; idx += 256) {
        int i = idx >> 6, c = idx & 63;
        sWk[c * 68 + i] = Wk[idx];
        sWq[c * 68 + i] = Wq[idx];
        sWw[c * 68 + i] = Ww[idx];
    }
    const int base = blockIdx.x * 32;
    for (int idx = tid; idx < 32 * 64; idx += 256) {
        int n = idx >> 6, c = idx & 63;
        int gn = base + n;
        sh[n * 68 + c] = (gn < N) ? h[(size_t)gn * 64 + c] : 0.f;
    }
    __syncthreads();

    const int grp = tid >> 6;
    const int col = tid & 63;

    float ak[8], aq[8], aw[8];
#pragma unroll
    for (int n = 0; n < 8; n++) { ak[n] = aq[n] = aw[n] = 0.f; }

    const float4* wk4 = (const float4*)(sWk + col * 68);
    const float4* wq4 = (const float4*)(sWq + col * 68);
    const float4* ww4 = (const float4*)(sWw + col * 68);

#pragma unroll
    for (int i4 = 0; i4 < 16; i4++) {
        const float4 wk = wk4[i4];
        const float4 wq = wq4[i4];
        const float4 ww = ww4[i4];
#pragma unroll
        for (int n = 0; n < 8; n++) {
            const float4 hv = *(const float4*)(sh + (grp * 8 + n) * 68 + i4 * 4);
            ak[n] += hv.x * wk.x + hv.y * wk.y + hv.z * wk.z + hv.w * wk.w;
            aq[n] += hv.x * wq.x + hv.y * wq.y + hv.z * wq.z + hv.w * wq.w;
            aw[n] += hv.x * ww.x + hv.y * ww.y + hv.z * ww.z + hv.w * ww.w;
        }
    }

#pragma unroll
    for (int n = 0; n < 8; n++) {
        int gn = base + grp * 8 + n;
        if (gn < N) {
            g_kw[(size_t)gn * 128 + col]      = ak[n];
            g_kw[(size_t)gn * 128 + 64 + col] = aw[n];
            g_q [(size_t)gn * 64 + col]       = aq[n];
        }
    }
}

// ---------------------------------------------------------------------------
// CSR construction: zero counts -> histogram -> 3-kernel exclusive scan -> scatter
// ---------------------------------------------------------------------------
__global__ void zero_cnt_kernel(int N)
{
    int i = blockIdx.x * blockDim.x + threadIdx.x;
    if (i < N) g_cnt[i] = 0;
}

__global__ void hist_kernel(const int* __restrict__ dst, int E)
{
    int i = blockIdx.x * blockDim.x + threadIdx.x;
    if (i < E) atomicAdd(&g_cnt[dst[i]], 1);
}

__global__ __launch_bounds__(256) void scan1_kernel(int N)
{
    __shared__ int s[256];
    const int t = threadIdx.x;
    const int i = blockIdx.x * 256 + t;
    int v = (i < N) ? g_cnt[i] : 0;
    s[t] = v;
    __syncthreads();
#pragma unroll
    for (int off = 1; off < 256; off <<= 1) {
        int x = (t >= off) ? s[t - off] : 0;
        __syncthreads();
        if (t >= off) s[t] += x;
        __syncthreads();
    }
    if (i < N) g_roff[i] = s[t] - v;     // exclusive within block
    if (t == 255) g_bsum[blockIdx.x] = s[255];
}

__global__ __launch_bounds__(512) void scan2_kernel(int nb)
{
    __shared__ int s[512];
    const int t = threadIdx.x;
    int v = (t < nb) ? g_bsum[t] : 0;
    s[t] = v;
    __syncthreads();
#pragma unroll
    for (int off = 1; off < 512; off <<= 1) {
        int x = (t >= off) ? s[t - off] : 0;
        __syncthreads();
        if (t >= off) s[t] += x;
        __syncthreads();
    }
    if (t < nb) g_boff[t] = s[t] - v;    // exclusive block offsets
}

__global__ void scan3_kernel(int N, int E)
{
    int i = blockIdx.x * blockDim.x + threadIdx.x;
    if (i < N) {
        int r = g_roff[i] + g_boff[i >> 8];
        g_roff[i] = r;
        g_cur[i]  = r;
    }
    if (i == 0) g_roff[N] = E;
}

__global__ void scatter_kernel(const int* __restrict__ src,
                               const int* __restrict__ dst, int E)
{
    int i = blockIdx.x * blockDim.x + threadIdx.x;
    if (i < E) {
        int p = atomicAdd(&g_cur[dst[i]], 1);
        g_esrc[p] = src[i];
    }
}

// ---------------------------------------------------------------------------
// Kernel: fused edge-softmax + aggregation. One warp per destination node.
// q[dst] lives in registers; per edge: load k|hw row (L2-resident), 4 head
// dots via shuffle reduce, one expf per 8-lane group, register accumulation.
// Writes each out row exactly once (bias + 1/z folded in). No atomics.
// ---------------------------------------------------------------------------
__global__ __launch_bounds__(256) void gather_kernel(
    const float* __restrict__ b,
    float* __restrict__ out,
    int N)
{
    const int w    = (blockIdx.x * 256 + threadIdx.x) >> 5;
    const int lane = threadIdx.x & 31;
    if (w >= N) return;
    const int n = w;

    const float2 q2 = ((const float2*)(g_q + (size_t)n * 64))[lane];
    const int p0 = g_roff[n];
    const int p1 = g_roff[n + 1];

    float2 acc0 = make_float2(0.f, 0.f), acc1 = acc0, acc2 = acc0, acc3 = acc0;
    float z0 = 0.f, z1 = 0.f, z2 = 0.f, z3 = 0.f;

    if (p0 < p1) {
        // software pipeline: prefetch edge p+1 while computing edge p
        int s = g_esrc[p0];
        const float2* kp = (const float2*)(g_kw + (size_t)s * 128);
        float2 k2 = kp[lane];
        float2 w2 = kp[lane + 32];

        for (int p = p0; p < p1; p++) {
            float2 k2n = k2, w2n = w2;
            if (p + 1 < p1) {
                int sn = g_esrc[p + 1];
                const float2* kpn = (const float2*)(g_kw + (size_t)sn * 128);
                k2n = kpn[lane];
                w2n = kpn[lane + 32];
            }

            // head h owns lanes [8h, 8h+8); reduce within 8-lane group
            float prod = k2.x * q2.x + k2.y * q2.y;
            prod += __shfl_xor_sync(0xffffffffu, prod, 4);
            prod += __shfl_xor_sync(0xffffffffu, prod, 2);
            prod += __shfl_xor_sync(0xffffffffu, prod, 1);
            const float pe = __expf(prod);   // one MUFU per lane-group value
            const float e0 = __shfl_sync(0xffffffffu, pe, 0);
            const float e1 = __shfl_sync(0xffffffffu, pe, 8);
            const float e2 = __shfl_sync(0xffffffffu, pe, 16);
            const float e3 = __shfl_sync(0xffffffffu, pe, 24);

            z0 += e0; z1 += e1; z2 += e2; z3 += e3;
            acc0.x += e0 * w2.x; acc0.y += e0 * w2.y;
            acc1.x += e1 * w2.x; acc1.y += e1 * w2.y;
            acc2.x += e2 * w2.x; acc2.y += e2 * w2.y;
            acc3.x += e3 * w2.x; acc3.y += e3 * w2.y;

            k2 = k2n; w2 = w2n;
        }
    }

    const float i0 = (z0 > 0.f) ? 1.f / z0 : 0.f;
    const float i1 = (z1 > 0.f) ? 1.f / z1 : 0.f;
    const float i2 = (z2 > 0.f) ? 1.f / z2 : 0.f;
    const float i3 = (z3 > 0.f) ? 1.f / z3 : 0.f;

    const float2 bb = ((const float2*)b)[lane];
    float* op = out + (size_t)n * 256;
    ((float2*)(op      ))[lane] = make_float2(acc0.x * i0 + bb.x, acc0.y * i0 + bb.y);
    ((float2*)(op +  64))[lane] = make_float2(acc1.x * i1 + bb.x, acc1.y * i1 + bb.y);
    ((float2*)(op + 128))[lane] = make_float2(acc2.x * i2 + bb.x, acc2.y * i2 + bb.y);
    ((float2*)(op + 192))[lane] = make_float2(acc3.x * i3 + bb.x, acc3.y * i3 + bb.y);
}

// ---------------------------------------------------------------------------
extern "C" void kernel_launch(void* const* d_in, const int* in_sizes, int n_in,
                              void* d_out, int out_size)
{
    const float* h   = (const float*)d_in[0];
    const int*   src = (const int*)  d_in[1];
    const int*   dst = (const int*)  d_in[2];
    const float* Wk  = (const float*)d_in[3];
    const float* Wq  = (const float*)d_in[4];
    const float* Ww  = (const float*)d_in[5];
    const float* b   = (const float*)d_in[6];
    float*       out = (float*)d_out;

    const int N  = in_sizes[0] / 64;
    const int E  = in_sizes[1];
    const int nb = (N + 255) / 256;

    zero_cnt_kernel<<<(N + 255) / 256, 256>>>(N);
    gemm3_kernel<<<(N + 31) / 32, 256>>>(h, Wk, Wq, Ww, N);
    hist_kernel<<<(E + 255) / 256, 256>>>(dst, E);
    scan1_kernel<<<nb, 256>>>(N);
    scan2_kernel<<<1, 512>>>(nb);
    scan3_kernel<<<(N + 255) / 256, 256>>>(N, E);
    scatter_kernel<<<(E + 255) / 256, 256>>>(src, dst, E);
    gather_kernel<<<(N + 7) / 8, 256>>>(b, out, N);
}